// round 4
// baseline (speedup 1.0000x reference)
#include <cuda_runtime.h>
#include <cstdint>

#define NMAX    50000
#define IN_DIM  256
#define W_DIM   128
#define BK      8

// QK row layout: per node, 128 floats of q then 128 floats of k (1KB/row)
__device__ float d_QK[(size_t)NMAX * 256];

// Packed fp32x2 FMA: d = a*b + d  (2 FMA lanes per instruction; Blackwell sm_100+)
#define FFMA2(d, a, b) \
    asm("fma.rn.f32x2 %0, %1, %2, %0;" : "+l"(d) : "l"(a), "l"(b))
#define FADD2(d, a) \
    asm("add.rn.f32x2 %0, %0, %1;" : "+l"(d) : "l"(a))

// ---------------------------------------------------------------------------
// Kernel 1: fused projection C[M,128] = X[M,256] @ W^T + b (W = wq or wk by
// blockIdx.y), written interleaved into d_QK.
// 128x128 tile, BK=8, 256 threads, 8x8 acc/thread held as 8x4 packed f32x2.
// A stored DUPLICATED in smem so packed (a,a) operands load directly (no MOVs).
// Double-buffered smem, register prefetch, one sync per k-tile.
// ---------------------------------------------------------------------------
__global__ __launch_bounds__(256) void sgemm_qk(
    const float* __restrict__ X,
    const float* __restrict__ Wq, const float* __restrict__ Bq,
    const float* __restrict__ Wk, const float* __restrict__ Bk,
    int M)
{
    __shared__ float As[2][BK][256];   // As[buf][k][2m] = As[buf][k][2m+1] = A[m][k]
    __shared__ float Bs[2][BK][128];   // Bs[buf][k][n]  = W[n][k]

    const float* __restrict__ W  = blockIdx.y ? Wk : Wq;
    const float* __restrict__ Bv = blockIdx.y ? Bk : Bq;

    const int tid  = threadIdx.x;
    const int tx   = tid & 15;          // n group (8 cols = 4 pairs)
    const int ty   = tid >> 4;          // m group (8 rows)
    const int row0 = blockIdx.x * 128;

    // loader mapping: each thread loads one float4 of A and one of B per tile
    const int l_row = tid >> 1;         // 0..127
    const int l_c4  = (tid & 1) * 4;    // 0 or 4
    const int gr    = row0 + l_row;
    const float* __restrict__ Xrow = X + (size_t)min(gr, M - 1) * IN_DIM;
    const bool   a_ok = (gr < M);
    const float* __restrict__ Wrow = W + (size_t)l_row * IN_DIM;

    unsigned long long c2[8][4];
    #pragma unroll
    for (int i = 0; i < 8; ++i)
        #pragma unroll
        for (int j = 0; j < 4; ++j) c2[i][j] = 0ull;

    // ---- prologue: load tile 0 ----
    float4 av = a_ok ? *(const float4*)(Xrow + l_c4) : make_float4(0.f,0.f,0.f,0.f);
    float4 bv = *(const float4*)(Wrow + l_c4);

    {
        float* ad = &As[0][l_c4][2 * l_row];
        ad[0] = av.x; ad[1] = av.x;
        ad = &As[0][l_c4 + 1][2 * l_row]; ad[0] = av.y; ad[1] = av.y;
        ad = &As[0][l_c4 + 2][2 * l_row]; ad[0] = av.z; ad[1] = av.z;
        ad = &As[0][l_c4 + 3][2 * l_row]; ad[0] = av.w; ad[1] = av.w;
        Bs[0][l_c4 + 0][l_row] = bv.x;
        Bs[0][l_c4 + 1][l_row] = bv.y;
        Bs[0][l_c4 + 2][l_row] = bv.z;
        Bs[0][l_c4 + 3][l_row] = bv.w;
    }
    __syncthreads();

    int buf = 0;
    for (int kt = BK; kt <= IN_DIM; kt += BK) {
        const bool has_next = (kt < IN_DIM);
        if (has_next) {
            av = a_ok ? *(const float4*)(Xrow + kt + l_c4) : make_float4(0.f,0.f,0.f,0.f);
            bv = *(const float4*)(Wrow + kt + l_c4);
        }

        // ---- compute on buf ----
        #pragma unroll
        for (int k = 0; k < BK; ++k) {
            // packed duplicated A: 8 m-values = 16 floats = 4 x LDS.128
            const ulonglong2* ap = (const ulonglong2*)&As[buf][k][ty * 16];
            const ulonglong2* bp = (const ulonglong2*)&Bs[buf][k][tx * 8];
            ulonglong2 a01 = ap[0], a23 = ap[1], a45 = ap[2], a67 = ap[3];
            ulonglong2 b01 = bp[0], b23 = bp[1];
            unsigned long long a2[8] = {a01.x, a01.y, a23.x, a23.y,
                                        a45.x, a45.y, a67.x, a67.y};
            unsigned long long b2[4] = {b01.x, b01.y, b23.x, b23.y};
            #pragma unroll
            for (int i = 0; i < 8; ++i) {
                FFMA2(c2[i][0], a2[i], b2[0]);
                FFMA2(c2[i][1], a2[i], b2[1]);
                FFMA2(c2[i][2], a2[i], b2[2]);
                FFMA2(c2[i][3], a2[i], b2[3]);
            }
        }

        if (has_next) {
            const int nb = buf ^ 1;
            float* ad = &As[nb][l_c4][2 * l_row];
            ad[0] = av.x; ad[1] = av.x;
            ad = &As[nb][l_c4 + 1][2 * l_row]; ad[0] = av.y; ad[1] = av.y;
            ad = &As[nb][l_c4 + 2][2 * l_row]; ad[0] = av.z; ad[1] = av.z;
            ad = &As[nb][l_c4 + 3][2 * l_row]; ad[0] = av.w; ad[1] = av.w;
            Bs[nb][l_c4 + 0][l_row] = bv.x;
            Bs[nb][l_c4 + 1][l_row] = bv.y;
            Bs[nb][l_c4 + 2][l_row] = bv.z;
            Bs[nb][l_c4 + 3][l_row] = bv.w;
            __syncthreads();
            buf = nb;
        }
    }

    // ---- epilogue: packed bias add, write interleaved QK ----
    unsigned long long bias2[4];
    {
        const ulonglong2* bvp = (const ulonglong2*)(Bv + tx * 8);
        ulonglong2 q0 = bvp[0], q1 = bvp[1];
        bias2[0] = q0.x; bias2[1] = q0.y; bias2[2] = q1.x; bias2[3] = q1.y;
    }

    #pragma unroll
    for (int i = 0; i < 8; ++i) {
        const int r = row0 + ty * 8 + i;
        if (r < M) {
            FADD2(c2[i][0], bias2[0]);
            FADD2(c2[i][1], bias2[1]);
            FADD2(c2[i][2], bias2[2]);
            FADD2(c2[i][3], bias2[3]);
            float* dst = d_QK + (size_t)r * 256 + blockIdx.y * 128 + tx * 8;
            ulonglong2 v0; v0.x = c2[i][0]; v0.y = c2[i][1];
            ulonglong2 v1; v1.x = c2[i][2]; v1.y = c2[i][3];
            *(ulonglong2*)(dst + 0) = v0;
            *(ulonglong2*)(dst + 4) = v1;
        }
    }
}

// ---------------------------------------------------------------------------
// Kernel 2: per-edge gather + dot. 8 lanes/edge, contiguous 128B float4 slabs,
// shfl reduce, leader writes /sqrt(128). edge_index is int32.
// ---------------------------------------------------------------------------
__global__ __launch_bounds__(256) void edge_attn(
    const int* __restrict__ ei,  // [2, E] int32
    float* __restrict__ out, int E, int M)
{
    const int e   = (blockIdx.x * blockDim.x + threadIdx.x) >> 3;
    const int sub = threadIdx.x & 7;
    if (e >= E) return;

    int s = ei[e];
    int d = ei[E + e];
    s = min(max(s, 0), M - 1);
    d = min(max(d, 0), M - 1);

    const float4* __restrict__ qp = (const float4*)(d_QK + (size_t)s * 256);
    const float4* __restrict__ kp = (const float4*)(d_QK + (size_t)d * 256 + 128);

    float acc = 0.f;
    #pragma unroll
    for (int it = 0; it < 4; ++it) {
        float4 q = qp[it * 8 + sub];
        float4 k = kp[it * 8 + sub];
        acc += q.x * k.x + q.y * k.y + q.z * k.z + q.w * k.w;
    }
    acc += __shfl_xor_sync(0xffffffffu, acc, 1);
    acc += __shfl_xor_sync(0xffffffffu, acc, 2);
    acc += __shfl_xor_sync(0xffffffffu, acc, 4);

    if (sub == 0)
        out[e] = acc * 0.08838834764831845f;   // 1/sqrt(128)
}

// ---------------------------------------------------------------------------
extern "C" void kernel_launch(void* const* d_in, const int* in_sizes, int n_in,
                              void* d_out, int out_size)
{
    // Resolve inputs by element count:
    //   node features ~12.8M fp32, weights 32768 fp32 (x2), biases 128 fp32 (x2),
    //   edge_index ~3.2M int32.
    const float *X = nullptr, *Wq = nullptr, *Bq = nullptr, *Wk = nullptr, *Bk = nullptr;
    const int   *ei = nullptr;
    int ei_elems = 0, x_elems = 0;

    for (int i = 0; i < n_in; ++i) {
        const int sz = in_sizes[i];
        if (sz == W_DIM * IN_DIM) {
            if (!Wq) Wq = (const float*)d_in[i];
            else     Wk = (const float*)d_in[i];
        } else if (sz == W_DIM) {
            if (!Bq) Bq = (const float*)d_in[i];
            else     Bk = (const float*)d_in[i];
        } else if (sz > 4000000) {
            X = (const float*)d_in[i];
            x_elems = sz;
        } else {
            ei = (const int*)d_in[i];
            ei_elems = sz;
        }
    }

    const int M = x_elems / IN_DIM;    // 50000
    const int E = ei_elems / 2;        // 1600000
    float* out = (float*)d_out;

    dim3 grid_g((M + 127) / 128, 2);
    sgemm_qk<<<grid_g, 256>>>(X, Wq, Bq, Wk, Bk, M);

    const int threads = 256;
    const int blocks  = (E * 8 + threads - 1) / threads;
    edge_attn<<<blocks, threads>>>(ei, out, E, M);
}

// round 7
// speedup vs baseline: 1.6018x; 1.6018x over previous
#include <cuda_runtime.h>
#include <cuda_fp16.h>
#include <cstdint>

#define NMAX    50000
#define IN_DIM  256
#define W_DIM   128
#define BM      128           // M rows per CTA
#define BN      128           // N cols per CTA (blockIdx.y -> Wq/Wk)
#define KC      64            // K chunk
#define AP      72            // padded row stride (halves) -> conflict-free LDS

// QK row layout: per node, 128 floats of q then 128 floats of k (1KB/row)
__device__ float d_QK[(size_t)NMAX * 256];

// smem offsets (bytes): four 128x72 half tiles
#define OFF_AHI 0
#define OFF_ALO (OFF_AHI + BM * AP * 2)
#define OFF_BHI (OFF_ALO + BM * AP * 2)
#define OFF_BLO (OFF_BHI + BN * AP * 2)
#define SMEM_TOTAL (OFF_BLO + BN * AP * 2)   // 73728 B

// m16n8k16 f16 MMA, fp32 accumulate (baseline PTX, works on sm_100 non-'a')
#define MMA16816(c, a, b)                                                     \
    asm volatile(                                                             \
        "mma.sync.aligned.m16n8k16.row.col.f32.f16.f16.f32 "                  \
        "{%0,%1,%2,%3}, {%4,%5,%6,%7}, {%8,%9}, {%0,%1,%2,%3};"               \
        : "+f"((c)[0]), "+f"((c)[1]), "+f"((c)[2]), "+f"((c)[3])              \
        : "r"((a)[0]), "r"((a)[1]), "r"((a)[2]), "r"((a)[3]),                 \
          "r"((b)[0]), "r"((b)[1]))

// ---------------------------------------------------------------------------
// Tensor-core projection: C[M,128] = X[M,256] @ W^T + b  (W = wq or wk).
// fp16 hi/lo split, 3 MMA terms -> ~1e-6 rel err. Output -> d_QK interleaved.
// ---------------------------------------------------------------------------
__global__ __launch_bounds__(256) void gemm_qk_mma(
    const float* __restrict__ X,
    const float* __restrict__ Wq, const float* __restrict__ Bq,
    const float* __restrict__ Wk, const float* __restrict__ Bk,
    int M)
{
    extern __shared__ char smem[];
    half* As_hi = (half*)(smem + OFF_AHI);
    half* As_lo = (half*)(smem + OFF_ALO);
    half* Bs_hi = (half*)(smem + OFF_BHI);
    half* Bs_lo = (half*)(smem + OFF_BLO);

    const float* __restrict__ W  = blockIdx.y ? Wk : Wq;
    const float* __restrict__ Bv = blockIdx.y ? Bk : Bq;

    const int tid  = threadIdx.x;
    const int wid  = tid >> 5;
    const int lane = tid & 31;
    const int g    = lane >> 2;        // 0..7
    const int t    = lane & 3;         // 0..3
    const int wm   = (wid & 3) * 32;   // warp m offset
    const int wn   = (wid >> 2) * 64;  // warp n offset
    const int row0 = blockIdx.x * BM;

    float c[2][8][4];
    #pragma unroll
    for (int mt = 0; mt < 2; ++mt)
        #pragma unroll
        for (int nt = 0; nt < 8; ++nt)
            #pragma unroll
            for (int i = 0; i < 4; ++i) c[mt][nt][i] = 0.f;

    for (int kc = 0; kc < IN_DIM; kc += KC) {
        __syncthreads();   // prev chunk compute done before restage

        // ---- stage A (128 x 64) and B (128 x 64) as hi/lo fp16 ----
        #pragma unroll 4
        for (int p = tid; p < BM * (KC / 2); p += 256) {
            const int r  = p >> 5;
            const int cl = (p & 31) << 1;
            const int gr = min(row0 + r, M - 1);
            float2 x = *(const float2*)(X + (size_t)gr * IN_DIM + kc + cl);
            half hx = __float2half_rn(x.x), hy = __float2half_rn(x.y);
            half lx = __float2half_rn(x.x - __half2float(hx));
            half ly = __float2half_rn(x.y - __half2float(hy));
            *(half2*)(As_hi + r * AP + cl) = __halves2half2(hx, hy);
            *(half2*)(As_lo + r * AP + cl) = __halves2half2(lx, ly);
        }
        #pragma unroll 4
        for (int p = tid; p < BN * (KC / 2); p += 256) {
            const int n  = p >> 5;
            const int cl = (p & 31) << 1;
            float2 x = *(const float2*)(W + (size_t)n * IN_DIM + kc + cl);
            half hx = __float2half_rn(x.x), hy = __float2half_rn(x.y);
            half lx = __float2half_rn(x.x - __half2float(hx));
            half ly = __float2half_rn(x.y - __half2float(hy));
            *(half2*)(Bs_hi + n * AP + cl) = __halves2half2(hx, hy);
            *(half2*)(Bs_lo + n * AP + cl) = __halves2half2(lx, ly);
        }
        __syncthreads();

        // ---- 4 k-steps of 16 over this chunk ----
        #pragma unroll
        for (int ks = 0; ks < KC / 16; ++ks) {
            const int kb = ks * 16 + 2 * t;

            uint32_t ah[2][4], al[2][4];
            #pragma unroll
            for (int mt = 0; mt < 2; ++mt) {
                const int rb = wm + mt * 16 + g;
                ah[mt][0] = *(const uint32_t*)(As_hi + (rb    ) * AP + kb);
                ah[mt][1] = *(const uint32_t*)(As_hi + (rb + 8) * AP + kb);
                ah[mt][2] = *(const uint32_t*)(As_hi + (rb    ) * AP + kb + 8);
                ah[mt][3] = *(const uint32_t*)(As_hi + (rb + 8) * AP + kb + 8);
                al[mt][0] = *(const uint32_t*)(As_lo + (rb    ) * AP + kb);
                al[mt][1] = *(const uint32_t*)(As_lo + (rb + 8) * AP + kb);
                al[mt][2] = *(const uint32_t*)(As_lo + (rb    ) * AP + kb + 8);
                al[mt][3] = *(const uint32_t*)(As_lo + (rb + 8) * AP + kb + 8);
            }

            uint32_t bh[8][2], bl[8][2];
            #pragma unroll
            for (int nt = 0; nt < 8; ++nt) {
                const int nb = wn + nt * 8 + g;
                bh[nt][0] = *(const uint32_t*)(Bs_hi + nb * AP + kb);
                bh[nt][1] = *(const uint32_t*)(Bs_hi + nb * AP + kb + 8);
                bl[nt][0] = *(const uint32_t*)(Bs_lo + nb * AP + kb);
                bl[nt][1] = *(const uint32_t*)(Bs_lo + nb * AP + kb + 8);
            }

            #pragma unroll
            for (int mt = 0; mt < 2; ++mt)
                #pragma unroll
                for (int nt = 0; nt < 8; ++nt) {
                    MMA16816(c[mt][nt], ah[mt], bh[nt]);
                    MMA16816(c[mt][nt], ah[mt], bl[nt]);
                    MMA16816(c[mt][nt], al[mt], bh[nt]);
                }
        }
    }

    // ---- epilogue: bias + store to interleaved QK ----
    #pragma unroll
    for (int mt = 0; mt < 2; ++mt) {
        const int r_lo = row0 + wm + mt * 16 + g;
        const int r_hi = r_lo + 8;
        #pragma unroll
        for (int nt = 0; nt < 8; ++nt) {
            const int col = wn + nt * 8 + 2 * t;
            const float2 bias = *(const float2*)(Bv + col);
            if (r_lo < M) {
                float2 v = make_float2(c[mt][nt][0] + bias.x, c[mt][nt][1] + bias.y);
                *(float2*)(d_QK + (size_t)r_lo * 256 + blockIdx.y * 128 + col) = v;
            }
            if (r_hi < M) {
                float2 v = make_float2(c[mt][nt][2] + bias.x, c[mt][nt][3] + bias.y);
                *(float2*)(d_QK + (size_t)r_hi * 256 + blockIdx.y * 128 + col) = v;
            }
        }
    }
}

// ---------------------------------------------------------------------------
// Per-edge gather + dot. 8 lanes/edge, contiguous 128B float4 slabs, shfl
// reduce, leader writes /sqrt(128). edge_index is int32.
// ---------------------------------------------------------------------------
__global__ __launch_bounds__(256) void edge_attn(
    const int* __restrict__ ei, float* __restrict__ out, int E, int M)
{
    const int e   = (blockIdx.x * blockDim.x + threadIdx.x) >> 3;
    const int sub = threadIdx.x & 7;
    if (e >= E) return;

    int s = ei[e];
    int d = ei[E + e];
    s = min(max(s, 0), M - 1);
    d = min(max(d, 0), M - 1);

    const float4* __restrict__ qp = (const float4*)(d_QK + (size_t)s * 256);
    const float4* __restrict__ kp = (const float4*)(d_QK + (size_t)d * 256 + 128);

    float acc = 0.f;
    #pragma unroll
    for (int it = 0; it < 4; ++it) {
        float4 q = qp[it * 8 + sub];
        float4 k = kp[it * 8 + sub];
        acc += q.x * k.x + q.y * k.y + q.z * k.z + q.w * k.w;
    }
    acc += __shfl_xor_sync(0xffffffffu, acc, 1);
    acc += __shfl_xor_sync(0xffffffffu, acc, 2);
    acc += __shfl_xor_sync(0xffffffffu, acc, 4);

    if (sub == 0)
        out[e] = acc * 0.08838834764831845f;   // 1/sqrt(128)
}

// ---------------------------------------------------------------------------
extern "C" void kernel_launch(void* const* d_in, const int* in_sizes, int n_in,
                              void* d_out, int out_size)
{
    const float *X = nullptr, *Wq = nullptr, *Bq = nullptr, *Wk = nullptr, *Bk = nullptr;
    const int   *ei = nullptr;
    int ei_elems = 0, x_elems = 0;

    for (int i = 0; i < n_in; ++i) {
        const int sz = in_sizes[i];
        if (sz == W_DIM * IN_DIM) {
            if (!Wq) Wq = (const float*)d_in[i];
            else     Wk = (const float*)d_in[i];
        } else if (sz == W_DIM) {
            if (!Bq) Bq = (const float*)d_in[i];
            else     Bk = (const float*)d_in[i];
        } else if (sz > 4000000) {
            X = (const float*)d_in[i];
            x_elems = sz;
        } else {
            ei = (const int*)d_in[i];
            ei_elems = sz;
        }
    }

    const int M = x_elems / IN_DIM;    // 50000
    const int E = ei_elems / 2;        // 1600000
    float* out = (float*)d_out;

    static int smem_set = 0;
    if (!smem_set) {
        cudaFuncSetAttribute(gemm_qk_mma,
                             cudaFuncAttributeMaxDynamicSharedMemorySize, SMEM_TOTAL);
        smem_set = 1;
    }

    dim3 grid_g((M + BM - 1) / BM, 2);
    gemm_qk_mma<<<grid_g, 256, SMEM_TOTAL>>>(X, Wq, Bq, Wk, Bk, M);

    const int threads = 256;
    const int blocks  = (E * 8 + threads - 1) / threads;
    edge_attn<<<blocks, threads>>>(ei, out, E, M);
}

// round 9
// speedup vs baseline: 1.8216x; 1.1372x over previous
#include <cuda_runtime.h>
#include <cuda_fp16.h>
#include <cstdint>

#define NMAX    50000
#define IN_DIM  256
#define W_DIM   128
#define BM      128           // M rows per CTA
#define BN      128           // N cols per CTA (blockIdx.y -> Wq/Wk)
#define KC      64            // K chunk
#define NCH     (IN_DIM / KC) // 4 chunks
#define AP      72            // padded row stride (halves): conflict-free LDS

// QK row layout: per node, 128 floats of q then 128 floats of k (1KB/row)
__device__ float d_QK[(size_t)NMAX * 256];
// Pre-converted packed weights: rows 0-127 = Wq, 128-255 = Wk  (fp16 hi/lo)
__device__ half d_Whi[256 * IN_DIM];
__device__ half d_Wlo[256 * IN_DIM];

// smem: [buf][4 tiles][BM*AP halves]; tiles: 0=Ahi 1=Alo 2=Bhi 3=Blo
#define TILE_H   (BM * AP)                    // 9216 halves
#define BUF_H    (4 * TILE_H)                 // 36864 halves
#define SMEM_TOTAL (2 * BUF_H * 2)            // 147456 B

// m16n8k16 f16 MMA, fp32 accumulate (baseline PTX, works on sm_100 non-'a')
#define MMA16816(c, a, b)                                                     \
    asm volatile(                                                             \
        "mma.sync.aligned.m16n8k16.row.col.f32.f16.f16.f32 "                  \
        "{%0,%1,%2,%3}, {%4,%5,%6,%7}, {%8,%9}, {%0,%1,%2,%3};"               \
        : "+f"((c)[0]), "+f"((c)[1]), "+f"((c)[2]), "+f"((c)[3])              \
        : "r"((a)[0]), "r"((a)[1]), "r"((a)[2]), "r"((a)[3]),                 \
          "r"((b)[0]), "r"((b)[1]))

// ---------------------------------------------------------------------------
// One-time weight pack+convert: [Wq;Wk] -> fp16 hi/lo, row-major [256,256].
// ---------------------------------------------------------------------------
__global__ __launch_bounds__(256) void prep_w(
    const float* __restrict__ Wq, const float* __restrict__ Wk)
{
    const int i = blockIdx.x * 256 + threadIdx.x;   // 0 .. 65535
    const int n = i >> 8, col = i & 255;
    const float v = (n < W_DIM) ? Wq[n * IN_DIM + col]
                                : Wk[(n - W_DIM) * IN_DIM + col];
    const half h = __float2half_rn(v);
    d_Whi[i] = h;
    d_Wlo[i] = __float2half_rn(v - __half2float(h));
}

// ---------------------------------------------------------------------------
// Tensor-core projection: C[M,128] = X[M,256] @ W^T + b  (W = wq or wk).
// fp16 hi/lo split, 3 MMA terms (~1e-6 rel err). Software-pipelined:
// prefetch chunk c+1 to regs, MMA chunk c, convert/store to buf^1, 1 sync.
// ---------------------------------------------------------------------------
__global__ __launch_bounds__(256) void gemm_qk_mma(
    const float* __restrict__ X,
    const float* __restrict__ Bq, const float* __restrict__ Bk,
    int M)
{
    extern __shared__ half sm[];
    const float* __restrict__ Bv = blockIdx.y ? Bk : Bq;

    const int tid  = threadIdx.x;
    const int wid  = tid >> 5;
    const int lane = tid & 31;
    const int g    = lane >> 2;        // 0..7
    const int t    = lane & 3;         // 0..3
    const int wm   = (wid & 3) * 32;   // warp m offset
    const int wn   = (wid >> 2) * 64;  // warp n offset
    const int row0 = blockIdx.x * BM;
    const int nbase = blockIdx.y * BN; // row offset into packed W

    // staging index maps (computed once)
    int a_r[8], a_c[8];                // A: 8 x float4 per thread (128x64 fp32)
    #pragma unroll
    for (int i = 0; i < 8; ++i) {
        const int p = tid + i * 256;
        a_r[i] = p >> 4; a_c[i] = (p & 15) * 4;
    }
    int b_n[4], b_c[4];                // B: 4 x uint4 (8 halves) per version
    #pragma unroll
    for (int i = 0; i < 4; ++i) {
        const int p = tid + i * 256;
        b_n[i] = p >> 3; b_c[i] = (p & 7) * 8;
    }

    float c[2][8][4];
    #pragma unroll
    for (int mt = 0; mt < 2; ++mt)
        #pragma unroll
        for (int nt = 0; nt < 8; ++nt)
            #pragma unroll
            for (int i = 0; i < 4; ++i) c[mt][nt][i] = 0.f;

    float4 ax[8];
    uint4  bh4[4], bl4[4];

    // ---- prologue: prefetch + stage chunk 0 into buf 0 ----
    #pragma unroll
    for (int i = 0; i < 8; ++i) {
        const int gr = min(row0 + a_r[i], M - 1);
        ax[i] = *(const float4*)(X + (size_t)gr * IN_DIM + a_c[i]);
    }
    #pragma unroll
    for (int i = 0; i < 4; ++i) {
        const size_t idx = (size_t)(nbase + b_n[i]) * IN_DIM + b_c[i];
        bh4[i] = *(const uint4*)(d_Whi + idx);
        bl4[i] = *(const uint4*)(d_Wlo + idx);
    }
    {
        half* As_hi = sm;            half* As_lo = sm + TILE_H;
        half* Bs_hi = sm + 2*TILE_H; half* Bs_lo = sm + 3*TILE_H;
        #pragma unroll
        for (int i = 0; i < 8; ++i) {
            const float4 x = ax[i];
            half2 h01 = __floats2half2_rn(x.x, x.y);
            half2 h23 = __floats2half2_rn(x.z, x.w);
            half2 l01 = __floats2half2_rn(x.x - __half2float(__low2half(h01)),
                                          x.y - __half2float(__high2half(h01)));
            half2 l23 = __floats2half2_rn(x.z - __half2float(__low2half(h23)),
                                          x.w - __half2float(__high2half(h23)));
            const int off = a_r[i] * AP + a_c[i];
            *(half2*)(As_hi + off) = h01; *(half2*)(As_hi + off + 2) = h23;
            *(half2*)(As_lo + off) = l01; *(half2*)(As_lo + off + 2) = l23;
        }
        #pragma unroll
        for (int i = 0; i < 4; ++i) {
            const int off = b_n[i] * AP + b_c[i];
            *(uint4*)(Bs_hi + off) = bh4[i];
            *(uint4*)(Bs_lo + off) = bl4[i];
        }
    }
    __syncthreads();

    // ---- main pipelined loop over 4 chunks ----
    for (int ch = 0; ch < NCH; ++ch) {
        const int kc_next = (ch + 1) * KC;
        if (ch < NCH - 1) {
            #pragma unroll
            for (int i = 0; i < 8; ++i) {
                const int gr = min(row0 + a_r[i], M - 1);
                ax[i] = *(const float4*)(X + (size_t)gr * IN_DIM + kc_next + a_c[i]);
            }
            #pragma unroll
            for (int i = 0; i < 4; ++i) {
                const size_t idx = (size_t)(nbase + b_n[i]) * IN_DIM + kc_next + b_c[i];
                bh4[i] = *(const uint4*)(d_Whi + idx);
                bl4[i] = *(const uint4*)(d_Wlo + idx);
            }
        }

        // MMA on current buffer
        {
            half* As_hi = sm + (ch & 1) * BUF_H;
            half* As_lo = As_hi + TILE_H;
            half* Bs_hi = As_hi + 2 * TILE_H;
            half* Bs_lo = As_hi + 3 * TILE_H;

            #pragma unroll
            for (int ks = 0; ks < KC / 16; ++ks) {
                const int kb = ks * 16 + 2 * t;

                uint32_t ah[2][4], al[2][4];
                #pragma unroll
                for (int mt = 0; mt < 2; ++mt) {
                    const int rb = wm + mt * 16 + g;
                    ah[mt][0] = *(const uint32_t*)(As_hi + (rb    ) * AP + kb);
                    ah[mt][1] = *(const uint32_t*)(As_hi + (rb + 8) * AP + kb);
                    ah[mt][2] = *(const uint32_t*)(As_hi + (rb    ) * AP + kb + 8);
                    ah[mt][3] = *(const uint32_t*)(As_hi + (rb + 8) * AP + kb + 8);
                    al[mt][0] = *(const uint32_t*)(As_lo + (rb    ) * AP + kb);
                    al[mt][1] = *(const uint32_t*)(As_lo + (rb + 8) * AP + kb);
                    al[mt][2] = *(const uint32_t*)(As_lo + (rb    ) * AP + kb + 8);
                    al[mt][3] = *(const uint32_t*)(As_lo + (rb + 8) * AP + kb + 8);
                }
                #pragma unroll
                for (int nt = 0; nt < 8; ++nt) {
                    const int nb = wn + nt * 8 + g;
                    uint32_t bh[2], bl[2];
                    bh[0] = *(const uint32_t*)(Bs_hi + nb * AP + kb);
                    bh[1] = *(const uint32_t*)(Bs_hi + nb * AP + kb + 8);
                    bl[0] = *(const uint32_t*)(Bs_lo + nb * AP + kb);
                    bl[1] = *(const uint32_t*)(Bs_lo + nb * AP + kb + 8);
                    #pragma unroll
                    for (int mt = 0; mt < 2; ++mt) {
                        MMA16816(c[mt][nt], ah[mt], bh);
                        MMA16816(c[mt][nt], ah[mt], bl);
                        MMA16816(c[mt][nt], al[mt], bh);
                    }
                }
            }
        }

        // convert + store next chunk into the other buffer
        if (ch < NCH - 1) {
            half* As_hi = sm + ((ch + 1) & 1) * BUF_H;
            half* As_lo = As_hi + TILE_H;
            half* Bs_hi = As_hi + 2 * TILE_H;
            half* Bs_lo = As_hi + 3 * TILE_H;
            #pragma unroll
            for (int i = 0; i < 8; ++i) {
                const float4 x = ax[i];
                half2 h01 = __floats2half2_rn(x.x, x.y);
                half2 h23 = __floats2half2_rn(x.z, x.w);
                half2 l01 = __floats2half2_rn(x.x - __half2float(__low2half(h01)),
                                              x.y - __half2float(__high2half(h01)));
                half2 l23 = __floats2half2_rn(x.z - __half2float(__low2half(h23)),
                                              x.w - __half2float(__high2half(h23)));
                const int off = a_r[i] * AP + a_c[i];
                *(half2*)(As_hi + off) = h01; *(half2*)(As_hi + off + 2) = h23;
                *(half2*)(As_lo + off) = l01; *(half2*)(As_lo + off + 2) = l23;
            }
            #pragma unroll
            for (int i = 0; i < 4; ++i) {
                const int off = b_n[i] * AP + b_c[i];
                *(uint4*)(Bs_hi + off) = bh4[i];
                *(uint4*)(Bs_lo + off) = bl4[i];
            }
        }
        __syncthreads();
    }

    // ---- epilogue: bias + store to interleaved QK ----
    #pragma unroll
    for (int mt = 0; mt < 2; ++mt) {
        const int r_lo = row0 + wm + mt * 16 + g;
        const int r_hi = r_lo + 8;
        #pragma unroll
        for (int nt = 0; nt < 8; ++nt) {
            const int col = wn + nt * 8 + 2 * t;
            const float2 bias = *(const float2*)(Bv + col);
            if (r_lo < M) {
                float2 v = make_float2(c[mt][nt][0] + bias.x, c[mt][nt][1] + bias.y);
                *(float2*)(d_QK + (size_t)r_lo * 256 + blockIdx.y * 128 + col) = v;
            }
            if (r_hi < M) {
                float2 v = make_float2(c[mt][nt][2] + bias.x, c[mt][nt][3] + bias.y);
                *(float2*)(d_QK + (size_t)r_hi * 256 + blockIdx.y * 128 + col) = v;
            }
        }
    }
}

// ---------------------------------------------------------------------------
// Per-edge gather + dot. 8 lanes/edge, contiguous 128B float4 slabs, shfl
// reduce, leader writes /sqrt(128). edge_index is int32.
// ---------------------------------------------------------------------------
__global__ __launch_bounds__(256) void edge_attn(
    const int* __restrict__ ei, float* __restrict__ out, int E, int M)
{
    const int e   = (blockIdx.x * blockDim.x + threadIdx.x) >> 3;
    const int sub = threadIdx.x & 7;
    if (e >= E) return;

    int s = ei[e];
    int d = ei[E + e];
    s = min(max(s, 0), M - 1);
    d = min(max(d, 0), M - 1);

    const float4* __restrict__ qp = (const float4*)(d_QK + (size_t)s * 256);
    const float4* __restrict__ kp = (const float4*)(d_QK + (size_t)d * 256 + 128);

    float acc = 0.f;
    #pragma unroll
    for (int it = 0; it < 4; ++it) {
        float4 q = qp[it * 8 + sub];
        float4 k = kp[it * 8 + sub];
        acc += q.x * k.x + q.y * k.y + q.z * k.z + q.w * k.w;
    }
    acc += __shfl_xor_sync(0xffffffffu, acc, 1);
    acc += __shfl_xor_sync(0xffffffffu, acc, 2);
    acc += __shfl_xor_sync(0xffffffffu, acc, 4);

    if (sub == 0)
        out[e] = acc * 0.08838834764831845f;   // 1/sqrt(128)
}

// ---------------------------------------------------------------------------
extern "C" void kernel_launch(void* const* d_in, const int* in_sizes, int n_in,
                              void* d_out, int out_size)
{
    const float *X = nullptr, *Wq = nullptr, *Bq = nullptr, *Wk = nullptr, *Bk = nullptr;
    const int   *ei = nullptr;
    int ei_elems = 0, x_elems = 0;

    for (int i = 0; i < n_in; ++i) {
        const int sz = in_sizes[i];
        if (sz == W_DIM * IN_DIM) {
            if (!Wq) Wq = (const float*)d_in[i];
            else     Wk = (const float*)d_in[i];
        } else if (sz == W_DIM) {
            if (!Bq) Bq = (const float*)d_in[i];
            else     Bk = (const float*)d_in[i];
        } else if (sz > 4000000) {
            X = (const float*)d_in[i];
            x_elems = sz;
        } else {
            ei = (const int*)d_in[i];
            ei_elems = sz;
        }
    }

    const int M = x_elems / IN_DIM;    // 50000
    const int E = ei_elems / 2;        // 1600000
    float* out = (float*)d_out;

    static int smem_set = 0;
    if (!smem_set) {
        cudaFuncSetAttribute(gemm_qk_mma,
                             cudaFuncAttributeMaxDynamicSharedMemorySize, SMEM_TOTAL);
        smem_set = 1;
    }

    prep_w<<<256, 256>>>(Wq, Wk);

    dim3 grid_g((M + BM - 1) / BM, 2);
    gemm_qk_mma<<<grid_g, 256, SMEM_TOTAL>>>(X, Bq, Bk, M);

    const int threads = 256;
    const int blocks  = (E * 8 + threads - 1) / threads;
    edge_attn<<<blocks, threads>>>(ei, out, E, M);
}